// round 5
// baseline (speedup 1.0000x reference)
#include <cuda_runtime.h>
#include <math.h>

// Problem constants (V=100000, E=1600000, C0=C1=16); V/E derived from in_sizes.
#define MAXV 100000

// Scratch (allocation-free rule: __device__ globals).
// g_feat: 4 float4 per node (64B, sector-aligned gather):
//   [0] = {d00, da, db, dself}   (x0 dots: w_n00, w_n01[:,0], w_n01[:,1], w_self0)
//   [1] = {X, Y, PA, PB}         (rotation pairs for w_n10 / p,q)
//   [2] = {RP, RQ, self1, self2} (rotation pair for r,s + self11 terms)
//   [3] = unused padding
__device__ float4 g_feat[MAXV * 4];
__device__ float4 g_acc[MAXV];   // {sum m0, sum mv1, sum mv2, degree}

__global__ void feat_kernel(const float* __restrict__ x,
                            const float* __restrict__ w_self0,
                            const float* __restrict__ w_n00,
                            const float* __restrict__ w_n10,
                            const float* __restrict__ w_self11,
                            const float* __restrict__ w_n01,
                            const float* __restrict__ w_n11,
                            int V)
{
    int v = blockIdx.x * blockDim.x + threadIdx.x;
    if (v >= V) return;
    const float* xr = x + (size_t)v * 48;

    float d00 = 0.f, da = 0.f, db = 0.f, ds = 0.f;
#pragma unroll
    for (int c = 0; c < 16; c++) {
        float x0 = xr[c];
        d00 = fmaf(x0, w_n00[c], d00);
        da  = fmaf(x0, w_n01[2 * c], da);
        db  = fmaf(x0, w_n01[2 * c + 1], db);
        ds  = fmaf(x0, w_self0[c], ds);
    }

    float X = 0.f, Y = 0.f, PA = 0.f, PB = 0.f, RP = 0.f, RQ = 0.f, s1 = 0.f, s2 = 0.f;
#pragma unroll
    for (int c = 0; c < 16; c++) {
        float a = xr[16 + 2 * c];
        float b = xr[17 + 2 * c];
        float wa = w_n10[2 * c],      wb = w_n10[2 * c + 1];
        float p  = w_n11[4 * c],      q  = w_n11[4 * c + 1];
        float r  = w_n11[4 * c + 2],  s  = w_n11[4 * c + 3];
        float sa = w_self11[2 * c],   sb = w_self11[2 * c + 1];
        X  = fmaf(a, wa,  fmaf(b, wb, X));
        Y  = fmaf(a, wb,  fmaf(-b, wa, Y));
        PA = fmaf(a, p,   fmaf(-b, q, PA));
        PB = fmaf(b, p,   fmaf(a, q, PB));
        RP = fmaf(a, r,   fmaf(b, s, RP));
        RQ = fmaf(a, s,   fmaf(-b, r, RQ));
        s1 = fmaf(a, sa,  fmaf(-b, sb, s1));
        s2 = fmaf(b, sa,  fmaf(a, sb, s2));
    }

    g_feat[4 * v + 0] = make_float4(d00, da, db, ds);
    g_feat[4 * v + 1] = make_float4(X, Y, PA, PB);
    g_feat[4 * v + 2] = make_float4(RP, RQ, s1, s2);
    g_acc[v] = make_float4(0.f, 0.f, 0.f, 0.f);  // zero accumulators here
}

__global__ void edge_kernel(const int* __restrict__ ei,
                            const float* __restrict__ angles,
                            const float* __restrict__ transp,
                            int E)
{
    int e = blockIdx.x * blockDim.x + threadIdx.x;
    if (e >= E) return;

    int src = ei[e];          // edge_index is int32 (JAX x64 disabled)
    int dst = ei[E + e];

    float st, ct, sg, cg;
    sincosf(angles[e], &st, &ct);
    sincosf(transp[e], &sg, &cg);
    float c2t = ct * ct - st * st;
    float s2t = 2.f * st * ct;

    float4 f0 = g_feat[4 * src + 0];
    float4 f1 = g_feat[4 * src + 1];
    float4 f2 = g_feat[4 * src + 2];

    // gauge-rotation of precomputed pairs by transporter angle
    float d1 = cg * f1.x + sg * f1.y;   // from (X, Y)
    float d2 = sg * f1.x - cg * f1.y;
    float A  = cg * f1.z - sg * f1.w;   // from (PA, PB)
    float B  = sg * f1.z + cg * f1.w;
    float P  = cg * f2.x + sg * f2.y;   // from (RP, RQ)
    float Q  = sg * f2.x - cg * f2.y;

    float m0  = f0.x + ct * d1 + st * d2;
    float mv1 = f0.y * ct - f0.z * st + A + c2t * P + s2t * Q;
    float mv2 = f0.y * st + f0.z * ct + B + s2t * P - c2t * Q;

    float4* addr = &g_acc[dst];
    asm volatile("red.global.add.v4.f32 [%0], {%1, %2, %3, %4};"
                 :: "l"(addr), "f"(m0), "f"(mv1), "f"(mv2), "f"(1.0f)
                 : "memory");
}

__global__ void out_kernel(const float* __restrict__ e1,
                           const float* __restrict__ e2,
                           float* __restrict__ out,
                           int V)
{
    int v = blockIdx.x * blockDim.x + threadIdx.x;
    if (v >= V) return;

    float4 a  = g_acc[v];
    float inv = 1.0f / fmaxf(a.w, 1.0f);
    float4 f0 = g_feat[4 * v + 0];
    float4 f2 = g_feat[4 * v + 2];

    float mag = a.x * inv + f0.w;
    float t1  = a.y * inv + f2.z;
    float t2  = a.z * inv + f2.w;
    float scale = 2.0f / (1.0f + expf(-mag));

    float s1 = t1 * scale, s2 = t2 * scale;
    out[3 * v + 0] = s1 * e1[3 * v + 0] + s2 * e2[3 * v + 0];
    out[3 * v + 1] = s1 * e1[3 * v + 1] + s2 * e2[3 * v + 1];
    out[3 * v + 2] = s1 * e1[3 * v + 2] + s2 * e2[3 * v + 2];
}

extern "C" void kernel_launch(void* const* d_in, const int* in_sizes, int n_in,
                              void* d_out, int out_size)
{
    const float* x        = (const float*)d_in[0];
    const int*   ei       = (const int*)d_in[1];     // int32 (see theory)
    const float* angles   = (const float*)d_in[2];
    const float* transp   = (const float*)d_in[3];
    const float* e1       = (const float*)d_in[4];
    const float* e2       = (const float*)d_in[5];
    const float* w_self0  = (const float*)d_in[6];
    const float* w_n00    = (const float*)d_in[7];
    const float* w_n10    = (const float*)d_in[8];
    const float* w_self11 = (const float*)d_in[9];
    const float* w_n01    = (const float*)d_in[10];
    const float* w_n11    = (const float*)d_in[11];
    float* out = (float*)d_out;

    int V = in_sizes[0] / 48;
    int E = in_sizes[2];

    feat_kernel<<<(V + 255) / 256, 256>>>(x, w_self0, w_n00, w_n10,
                                          w_self11, w_n01, w_n11, V);
    edge_kernel<<<(E + 255) / 256, 256>>>(ei, angles, transp, E);
    out_kernel<<<(V + 255) / 256, 256>>>(e1, e2, out, V);
}

// round 8
// speedup vs baseline: 1.3339x; 1.3339x over previous
#include <cuda_runtime.h>
#include <math.h>

#define MAXV 100000

// Scratch (allocation-free rule: __device__ globals).
// g_feat: 4 float4 per node (64B stride, sector-aligned gather; [3] is pad):
//   [0] = {d00, da, db, dself}
//   [1] = {X, Y, PA, PB}
//   [2] = {RP, RQ, self1, self2}
__device__ float4 g_feat[MAXV * 4];
__device__ float4 g_acc[MAXV];   // {sum m0, sum mv1, sum mv2, degree}

// Shared-memory weight layout offsets
#define W_N00    0     // 16
#define W_N01    16    // 32
#define W_SELF0  48    // 16
#define W_N10    64    // 32
#define W_N11    96    // 64
#define W_SELF11 160   // 32  -> total 192

__global__ void feat_kernel(const float* __restrict__ x,
                            const float* __restrict__ w_self0,
                            const float* __restrict__ w_n00,
                            const float* __restrict__ w_n10,
                            const float* __restrict__ w_self11,
                            const float* __restrict__ w_n01,
                            const float* __restrict__ w_n11,
                            int V)
{
    __shared__ float sw[192];
    int t = threadIdx.x;
    if (t < 192) {
        float val;
        if      (t < 16)  val = w_n00[t];
        else if (t < 48)  val = w_n01[t - 16];
        else if (t < 64)  val = w_self0[t - 48];
        else if (t < 96)  val = w_n10[t - 64];
        else if (t < 160) val = w_n11[t - 96];
        else              val = w_self11[t - 160];
        sw[t] = val;
    }
    __syncthreads();

    int v = blockIdx.x * blockDim.x + threadIdx.x;
    if (v >= V) return;

    // Vectorized row load: 12 LDG.128 (row base is 192B -> 16B aligned)
    const float4* xr4 = (const float4*)(x + (size_t)v * 48);
    float4 xv[12];
#pragma unroll
    for (int i = 0; i < 12; i++) xv[i] = xr4[i];
    const float* xr = (const float*)xv;

    float d00 = 0.f, da = 0.f, db = 0.f, ds = 0.f;
#pragma unroll
    for (int c = 0; c < 16; c++) {
        float x0 = xr[c];
        d00 = fmaf(x0, sw[W_N00 + c], d00);
        da  = fmaf(x0, sw[W_N01 + 2 * c], da);
        db  = fmaf(x0, sw[W_N01 + 2 * c + 1], db);
        ds  = fmaf(x0, sw[W_SELF0 + c], ds);
    }

    float X = 0.f, Y = 0.f, PA = 0.f, PB = 0.f, RP = 0.f, RQ = 0.f, s1 = 0.f, s2 = 0.f;
#pragma unroll
    for (int c = 0; c < 16; c++) {
        float a = xr[16 + 2 * c];
        float b = xr[17 + 2 * c];
        float wa = sw[W_N10 + 2 * c],     wb = sw[W_N10 + 2 * c + 1];
        float p  = sw[W_N11 + 4 * c],     q  = sw[W_N11 + 4 * c + 1];
        float r  = sw[W_N11 + 4 * c + 2], s  = sw[W_N11 + 4 * c + 3];
        float sa = sw[W_SELF11 + 2 * c],  sb = sw[W_SELF11 + 2 * c + 1];
        X  = fmaf(a, wa,  fmaf(b, wb, X));
        Y  = fmaf(a, wb,  fmaf(-b, wa, Y));
        PA = fmaf(a, p,   fmaf(-b, q, PA));
        PB = fmaf(b, p,   fmaf(a, q, PB));
        RP = fmaf(a, r,   fmaf(b, s, RP));
        RQ = fmaf(a, s,   fmaf(-b, r, RQ));
        s1 = fmaf(a, sa,  fmaf(-b, sb, s1));
        s2 = fmaf(b, sa,  fmaf(a, sb, s2));
    }

    g_feat[4 * v + 0] = make_float4(d00, da, db, ds);
    g_feat[4 * v + 1] = make_float4(X, Y, PA, PB);
    g_feat[4 * v + 2] = make_float4(RP, RQ, s1, s2);
    g_acc[v] = make_float4(0.f, 0.f, 0.f, 0.f);
}

__device__ __forceinline__ void process_edge(int src, int dst, float ang, float tr)
{
    float st, ct, sg, cg;
    __sincosf(ang, &st, &ct);   // args in [0, 2pi) -> MUFU fast path is accurate enough
    __sincosf(tr,  &sg, &cg);
    float c2t = ct * ct - st * st;
    float s2t = 2.f * st * ct;

    float4 f0 = g_feat[4 * src + 0];
    float4 f1 = g_feat[4 * src + 1];
    float4 f2 = g_feat[4 * src + 2];

    float d1 = cg * f1.x + sg * f1.y;
    float d2 = sg * f1.x - cg * f1.y;
    float A  = cg * f1.z - sg * f1.w;
    float B  = sg * f1.z + cg * f1.w;
    float P  = cg * f2.x + sg * f2.y;
    float Q  = sg * f2.x - cg * f2.y;

    float m0  = f0.x + ct * d1 + st * d2;
    float mv1 = f0.y * ct - f0.z * st + A + c2t * P + s2t * Q;
    float mv2 = f0.y * st + f0.z * ct + B + s2t * P - c2t * Q;

    float4* addr = &g_acc[dst];
    asm volatile("red.global.add.v4.f32 [%0], {%1, %2, %3, %4};"
                 :: "l"(addr), "f"(m0), "f"(mv1), "f"(mv2), "f"(1.0f)
                 : "memory");
}

__global__ void edge_kernel(const int* __restrict__ ei,
                            const float* __restrict__ angles,
                            const float* __restrict__ transp,
                            int E)
{
    int i = blockIdx.x * blockDim.x + threadIdx.x;
    int e = 2 * i;
    if (e >= E) return;

    if (e + 1 < E) {
        // vector loads (e is even -> 8B aligned; E assumed even for the dst row)
        int2   sp = *(const int2*)(ei + e);
        int2   dp = *(const int2*)(ei + (size_t)E + e);
        float2 an = *(const float2*)(angles + e);
        float2 tp = *(const float2*)(transp + e);
        process_edge(sp.x, dp.x, an.x, tp.x);
        process_edge(sp.y, dp.y, an.y, tp.y);
    } else {
        process_edge(ei[e], ei[(size_t)E + e], angles[e], transp[e]);
    }
}

__global__ void out_kernel(const float* __restrict__ e1,
                           const float* __restrict__ e2,
                           float* __restrict__ out,
                           int V)
{
    int v = blockIdx.x * blockDim.x + threadIdx.x;
    if (v >= V) return;

    float4 a  = g_acc[v];
    float inv = 1.0f / fmaxf(a.w, 1.0f);
    float4 f0 = g_feat[4 * v + 0];
    float4 f2 = g_feat[4 * v + 2];

    float mag = a.x * inv + f0.w;
    float t1  = a.y * inv + f2.z;
    float t2  = a.z * inv + f2.w;
    float scale = __fdividef(2.0f, 1.0f + __expf(-mag));

    float s1 = t1 * scale, s2 = t2 * scale;
    out[3 * v + 0] = s1 * e1[3 * v + 0] + s2 * e2[3 * v + 0];
    out[3 * v + 1] = s1 * e1[3 * v + 1] + s2 * e2[3 * v + 1];
    out[3 * v + 2] = s1 * e1[3 * v + 2] + s2 * e2[3 * v + 2];
}

extern "C" void kernel_launch(void* const* d_in, const int* in_sizes, int n_in,
                              void* d_out, int out_size)
{
    const float* x        = (const float*)d_in[0];
    const int*   ei       = (const int*)d_in[1];
    const float* angles   = (const float*)d_in[2];
    const float* transp   = (const float*)d_in[3];
    const float* e1       = (const float*)d_in[4];
    const float* e2       = (const float*)d_in[5];
    const float* w_self0  = (const float*)d_in[6];
    const float* w_n00    = (const float*)d_in[7];
    const float* w_n10    = (const float*)d_in[8];
    const float* w_self11 = (const float*)d_in[9];
    const float* w_n01    = (const float*)d_in[10];
    const float* w_n11    = (const float*)d_in[11];
    float* out = (float*)d_out;

    int V = in_sizes[0] / 48;
    int E = in_sizes[2];

    feat_kernel<<<(V + 255) / 256, 256>>>(x, w_self0, w_n00, w_n10,
                                          w_self11, w_n01, w_n11, V);
    int pairs = (E + 1) / 2;
    edge_kernel<<<(pairs + 255) / 256, 256>>>(ei, angles, transp, E);
    out_kernel<<<(V + 255) / 256, 256>>>(e1, e2, out, V);
}